// round 5
// baseline (speedup 1.0000x reference)
#include <cuda_runtime.h>
#include <cuda_bf16.h>
#include <math.h>

// Problem constants
constexpr int cT = 256;
constexpr int cB = 64;
constexpr int cI = 512;
constexpr int cH = 1024;
constexpr int cD = 100;
constexpr float cALPHA = 0.5f;

// ---------------- scratch (device globals; no allocation allowed) ----------
__device__ float g_Xg[(size_t)cT * cB * 4 * cH];  // x @ Wx + b   [T,B,4H]  (256 MB)
__device__ float g_Xr[(size_t)cT * cB * cD];      // x @ Wrx      [T,B,D]
__device__ float g_G [(size_t)cB * 4 * cH];       // gates preact [B,4H]
__device__ float g_h [(size_t)cB * cH];
__device__ float g_c [(size_t)cB * cH];
__device__ float g_d [(size_t)cB * cD];

__device__ __forceinline__ float sigmoidf_(float x) {
    return 1.0f / (1.0f + expf(-x));
}

// ---------------------------------------------------------------------------
// P1: g_Xg[t*b, n] = sum_k x[t*b, k] * Wx[k, n] + bias[n]
// M=16384, N=4096, K=512. Classic 128x128x8 tiled sgemm, 8x8 per thread.
// ---------------------------------------------------------------------------
__global__ __launch_bounds__(256) void p1_xwx_kernel(
    const float* __restrict__ A,    // x  [M,K]
    const float* __restrict__ Bm,   // Wx [K,N]
    const float* __restrict__ bias) // b  [N]
{
    constexpr int M = cT * cB;   // 16384
    constexpr int N = 4 * cH;    // 4096
    constexpr int K = cI;        // 512

    __shared__ float As[8][128];
    __shared__ float Bs[8][128];

    const int tid = threadIdx.x;
    const int bm = blockIdx.y * 128;
    const int bn = blockIdx.x * 128;
    const int tx = tid & 15;   // 0..15
    const int ty = tid >> 4;   // 0..15

    float acc[8][8];
#pragma unroll
    for (int i = 0; i < 8; i++)
#pragma unroll
        for (int j = 0; j < 8; j++) acc[i][j] = 0.0f;

    const int arow = tid >> 1;        // 0..127
    const int acol = (tid & 1) * 4;   // 0 or 4
    const int brow = tid >> 5;        // 0..7
    const int bcol = (tid & 31) * 4;  // 0..124

    for (int k0 = 0; k0 < K; k0 += 8) {
        float4 a = *(const float4*)(A + (size_t)(bm + arow) * K + k0 + acol);
        As[acol + 0][arow] = a.x;
        As[acol + 1][arow] = a.y;
        As[acol + 2][arow] = a.z;
        As[acol + 3][arow] = a.w;
        *(float4*)(&Bs[brow][bcol]) =
            *(const float4*)(Bm + (size_t)(k0 + brow) * N + bn + bcol);
        __syncthreads();
#pragma unroll
        for (int k = 0; k < 8; k++) {
            float4 a0 = *(float4*)&As[k][ty * 8];
            float4 a1 = *(float4*)&As[k][ty * 8 + 4];
            float4 b0 = *(float4*)&Bs[k][tx * 8];
            float4 b1 = *(float4*)&Bs[k][tx * 8 + 4];
            float ar[8] = {a0.x, a0.y, a0.z, a0.w, a1.x, a1.y, a1.z, a1.w};
            float br[8] = {b0.x, b0.y, b0.z, b0.w, b1.x, b1.y, b1.z, b1.w};
#pragma unroll
            for (int i = 0; i < 8; i++)
#pragma unroll
                for (int j = 0; j < 8; j++) acc[i][j] += ar[i] * br[j];
        }
        __syncthreads();
    }

#pragma unroll
    for (int i = 0; i < 8; i++) {
        const int row = bm + ty * 8 + i;
#pragma unroll
        for (int j = 0; j < 8; j += 4) {
            const int col = bn + tx * 8 + j;
            float4 v;
            v.x = acc[i][j + 0] + bias[col + 0];
            v.y = acc[i][j + 1] + bias[col + 1];
            v.z = acc[i][j + 2] + bias[col + 2];
            v.w = acc[i][j + 3] + bias[col + 3];
            *(float4*)(g_Xg + (size_t)row * N + col) = v;
        }
    }
}

// ---------------------------------------------------------------------------
// P2: g_Xr[row, j] = sum_k x[row, k] * Wrx[k, j]   (M=16384, N=100, K=512)
// Block handles 16 rows; x tile in shared; Wrx value reused across 16 rows.
// ---------------------------------------------------------------------------
__global__ __launch_bounds__(128) void p2_xwrx_kernel(
    const float* __restrict__ x, const float* __restrict__ Wrx)
{
    __shared__ float xs[16][cI];   // 32 KB
    const int row0 = blockIdx.x * 16;
    const int tid = threadIdx.x;

    for (int i = tid; i < 16 * cI / 4; i += 128) {
        const int r = i / (cI / 4);
        const int c = i % (cI / 4);
        ((float4*)xs[r])[c] = ((const float4*)(x + (size_t)(row0 + r) * cI))[c];
    }
    __syncthreads();

    if (tid < cD) {
        float acc[16];
#pragma unroll
        for (int r = 0; r < 16; r++) acc[r] = 0.0f;
        for (int k = 0; k < cI; k += 4) {
            float w0 = Wrx[(k + 0) * cD + tid];
            float w1 = Wrx[(k + 1) * cD + tid];
            float w2 = Wrx[(k + 2) * cD + tid];
            float w3 = Wrx[(k + 3) * cD + tid];
#pragma unroll
            for (int r = 0; r < 16; r++) {
                float4 xv = *(float4*)&xs[r][k];
                acc[r] += xv.x * w0 + xv.y * w1 + xv.z * w2 + xv.w * w3;
            }
        }
#pragma unroll
        for (int r = 0; r < 16; r++)
            g_Xr[(size_t)(row0 + r) * cD + tid] = acc[r];
    }
}

// ---------------------------------------------------------------------------
// init: h = h0, c = c0, d = d0
// ---------------------------------------------------------------------------
__global__ void init_kernel(const float* __restrict__ h0,
                            const float* __restrict__ c0,
                            const float* __restrict__ d0)
{
    const int idx = blockIdx.x * blockDim.x + threadIdx.x;
    if (idx < cB * cH) {
        g_h[idx] = h0[idx];
        g_c[idx] = c0[idx];
    }
    if (idx < cB * cD) g_d[idx] = d0[idx];
}

// ---------------------------------------------------------------------------
// S1a: g_G[b,n] = g_Xg[t,b,n] + sum_k g_h[b,k] * Wh[k,n]
// M=64 (all of B), N=4096, K=1024. BM=64, BN=32, BK=16, 256 threads, 4x2/thr.
// grid = 128 blocks.
// ---------------------------------------------------------------------------
__global__ __launch_bounds__(256) void s1a_gates_kernel(
    const float* __restrict__ Wh, int t)
{
    constexpr int N = 4 * cH;   // 4096
    constexpr int K = cH;       // 1024

    __shared__ float As[16][64];
    __shared__ float Bs[16][32];

    const int tid = threadIdx.x;
    const int bn = blockIdx.x * 32;
    const int tx = tid & 15;   // n-group: cols tx*2..+1
    const int ty = tid >> 4;   // m-group: rows ty*4..+3

    float acc[4][2];
#pragma unroll
    for (int i = 0; i < 4; i++) { acc[i][0] = 0.0f; acc[i][1] = 0.0f; }

    const int arow = tid >> 2;        // 0..63
    const int acol = (tid & 3) * 4;   // 0,4,8,12
    const int brow = tid >> 4;        // 0..15
    const int bcol = (tid & 15) * 2;  // 0..30

    for (int k0 = 0; k0 < K; k0 += 16) {
        float4 a = *(const float4*)(g_h + (size_t)arow * K + k0 + acol);
        As[acol + 0][arow] = a.x;
        As[acol + 1][arow] = a.y;
        As[acol + 2][arow] = a.z;
        As[acol + 3][arow] = a.w;
        *(float2*)&Bs[brow][bcol] =
            *(const float2*)(Wh + (size_t)(k0 + brow) * N + bn + bcol);
        __syncthreads();
#pragma unroll
        for (int k = 0; k < 16; k++) {
            float4 av = *(float4*)&As[k][ty * 4];
            float2 bv = *(float2*)&Bs[k][tx * 2];
            acc[0][0] += av.x * bv.x;  acc[0][1] += av.x * bv.y;
            acc[1][0] += av.y * bv.x;  acc[1][1] += av.y * bv.y;
            acc[2][0] += av.z * bv.x;  acc[2][1] += av.z * bv.y;
            acc[3][0] += av.w * bv.x;  acc[3][1] += av.w * bv.y;
        }
        __syncthreads();
    }

    const float* add = g_Xg + (size_t)t * cB * N;
#pragma unroll
    for (int i = 0; i < 4; i++) {
        const int row = ty * 4 + i;
        const int col = bn + tx * 2;
        float2 v;
        v.x = acc[i][0] + add[(size_t)row * N + col + 0];
        v.y = acc[i][1] + add[(size_t)row * N + col + 1];
        *(float2*)(g_G + (size_t)row * N + col) = v;
    }
}

// ---------------------------------------------------------------------------
// S1b: r = sigmoid(g_Xr[t,b,:] + 0.5 * h@Wrh);  d := r * d   (in place)
// 64 blocks (one per b), 128 threads (j = tid < 100).
// ---------------------------------------------------------------------------
__global__ __launch_bounds__(128) void s1b_rd_kernel(
    const float* __restrict__ Wrh, int t)
{
    __shared__ float hs[cH];
    const int b = blockIdx.x;
    const int tid = threadIdx.x;

    for (int i = tid; i < cH / 4; i += 128)
        ((float4*)hs)[i] = ((const float4*)(g_h + (size_t)b * cH))[i];
    __syncthreads();

    if (tid < cD) {
        float a0 = 0.f, a1 = 0.f, a2 = 0.f, a3 = 0.f;
        for (int k = 0; k < cH; k += 4) {
            a0 += hs[k + 0] * Wrh[(k + 0) * cD + tid];
            a1 += hs[k + 1] * Wrh[(k + 1) * cD + tid];
            a2 += hs[k + 2] * Wrh[(k + 2) * cD + tid];
            a3 += hs[k + 3] * Wrh[(k + 3) * cD + tid];
        }
        const float pre = g_Xr[(size_t)t * cB * cD + b * cD + tid]
                        + cALPHA * ((a0 + a1) + (a2 + a3));
        const float r = sigmoidf_(pre);
        g_d[b * cD + tid] = r * g_d[b * cD + tid];
    }
}

// ---------------------------------------------------------------------------
// S2: u = d_new @ Wd;  c := sig(f)*c + sig(i)*tanh(g) + tanh(u);
//     h := sig(o)*tanh(c);  out[t] = h
// 64 blocks (one per b), 256 threads, 4 hidden elems per thread.
// ---------------------------------------------------------------------------
__global__ __launch_bounds__(256) void s2_update_kernel(
    const float* __restrict__ Wd, float* __restrict__ out, int t)
{
    __shared__ float dn[cD];
    const int b = blockIdx.x;
    const int tid = threadIdx.x;

    if (tid < cD) dn[tid] = g_d[b * cD + tid];
    __syncthreads();

    float u[4] = {0.f, 0.f, 0.f, 0.f};
    for (int j = 0; j < cD; j++) {
        const float dv = dn[j];
        const float* wrow = Wd + (size_t)j * cH + tid;
        u[0] += dv * wrow[0];
        u[1] += dv * wrow[256];
        u[2] += dv * wrow[512];
        u[3] += dv * wrow[768];
    }

    const float* Gb = g_G + (size_t)b * 4 * cH;
#pragma unroll
    for (int rep = 0; rep < 4; rep++) {
        const int hx = tid + rep * 256;
        const float ig = sigmoidf_(Gb[hx]);
        const float fg = sigmoidf_(Gb[cH + hx]);
        const float gg = tanhf(Gb[2 * cH + hx]);
        const float og = sigmoidf_(Gb[3 * cH + hx]);
        float c = fg * g_c[(size_t)b * cH + hx] + ig * gg + tanhf(u[rep]);
        g_c[(size_t)b * cH + hx] = c;
        const float hn = og * tanhf(c);
        g_h[(size_t)b * cH + hx] = hn;
        out[(size_t)t * cB * cH + (size_t)b * cH + hx] = hn;
    }
}

// ---------------------------------------------------------------------------
// finalize: append final h, c, d after the T*B*H outputs
// ---------------------------------------------------------------------------
__global__ void finalize_kernel(float* __restrict__ out)
{
    const int idx = blockIdx.x * blockDim.x + threadIdx.x;
    const size_t base = (size_t)cT * cB * cH;
    if (idx < cB * cH) {
        out[base + idx] = g_h[idx];
        out[base + cB * cH + idx] = g_c[idx];
    }
    if (idx < cB * cD) out[base + 2 * (size_t)cB * cH + idx] = g_d[idx];
}

// ---------------------------------------------------------------------------
extern "C" void kernel_launch(void* const* d_in, const int* in_sizes, int n_in,
                              void* d_out, int out_size)
{
    const float* x   = (const float*)d_in[0];
    const float* h0  = (const float*)d_in[1];
    const float* c0  = (const float*)d_in[2];
    const float* d0  = (const float*)d_in[3];
    const float* Wx  = (const float*)d_in[4];
    const float* Wh  = (const float*)d_in[5];
    const float* bb  = (const float*)d_in[6];
    const float* Wrx = (const float*)d_in[7];
    const float* Wrh = (const float*)d_in[8];
    const float* Wd  = (const float*)d_in[9];
    float* out = (float*)d_out;

    // init state
    init_kernel<<<(cB * cH + 255) / 256, 256>>>(h0, c0, d0);

    // precompute input projections (parallel over all T)
    {
        dim3 grid(4 * cH / 128, cT * cB / 128);  // (32, 128)
        p1_xwx_kernel<<<grid, 256>>>(x, Wx, bb);
    }
    p2_xwrx_kernel<<<cT * cB / 16, 128>>>(x, Wrx);

    // sequential scan
    for (int t = 0; t < cT; t++) {
        s1a_gates_kernel<<<128, 256>>>(Wh, t);
        s1b_rd_kernel<<<cB, 128>>>(Wrh, t);
        s2_update_kernel<<<cB, 256>>>(Wd, out, t);
    }

    // tail: final h, c, d (only if the harness expects them)
    const long long full = (long long)cT * cB * cH + 2LL * cB * cH + (long long)cB * cD;
    if ((long long)out_size >= full)
        finalize_kernel<<<(cB * cH + 255) / 256, 256>>>(out);
}

// round 7
// speedup vs baseline: 1.0019x; 1.0019x over previous
#include <cuda_runtime.h>
#include <cuda_bf16.h>
#include <math.h>

// Problem constants
constexpr int cT = 256;
constexpr int cB = 64;
constexpr int cI = 512;
constexpr int cH = 1024;
constexpr int cD = 100;
constexpr float cALPHA = 0.5f;

// ---------------- scratch (device globals; no allocation allowed) ----------
__device__ float g_Xg[(size_t)cT * cB * 4 * cH];  // x @ Wx + b   [T,B,4H]  (256 MB)
__device__ float g_Xr[(size_t)cT * cB * cD];      // x @ Wrx      [T,B,D]
__device__ float g_G [(size_t)cB * 4 * cH];       // gates preact [B,4H]
__device__ float g_h [(size_t)cB * cH];
__device__ float g_c [(size_t)cB * cH];
__device__ float g_d [(size_t)cB * cD];

__device__ __forceinline__ float sigmoidf_(float x) {
    return 1.0f / (1.0f + expf(-x));
}

// ---------------------------------------------------------------------------
// P1: g_Xg[t*b, n] = sum_k x[t*b, k] * Wx[k, n] + bias[n]
// M=16384, N=4096, K=512. Classic 128x128x8 tiled sgemm, 8x8 per thread.
// ---------------------------------------------------------------------------
__global__ __launch_bounds__(256) void p1_xwx_kernel(
    const float* __restrict__ A,    // x  [M,K]
    const float* __restrict__ Bm,   // Wx [K,N]
    const float* __restrict__ bias) // b  [N]
{
    constexpr int M = cT * cB;   // 16384
    constexpr int N = 4 * cH;    // 4096
    constexpr int K = cI;        // 512

    __shared__ float As[8][128];
    __shared__ float Bs[8][128];

    const int tid = threadIdx.x;
    const int bm = blockIdx.y * 128;
    const int bn = blockIdx.x * 128;
    const int tx = tid & 15;   // 0..15
    const int ty = tid >> 4;   // 0..15

    float acc[8][8];
#pragma unroll
    for (int i = 0; i < 8; i++)
#pragma unroll
        for (int j = 0; j < 8; j++) acc[i][j] = 0.0f;

    const int arow = tid >> 1;        // 0..127
    const int acol = (tid & 1) * 4;   // 0 or 4
    const int brow = tid >> 5;        // 0..7
    const int bcol = (tid & 31) * 4;  // 0..124

    for (int k0 = 0; k0 < K; k0 += 8) {
        float4 a = *(const float4*)(A + (size_t)(bm + arow) * K + k0 + acol);
        As[acol + 0][arow] = a.x;
        As[acol + 1][arow] = a.y;
        As[acol + 2][arow] = a.z;
        As[acol + 3][arow] = a.w;
        *(float4*)(&Bs[brow][bcol]) =
            *(const float4*)(Bm + (size_t)(k0 + brow) * N + bn + bcol);
        __syncthreads();
#pragma unroll
        for (int k = 0; k < 8; k++) {
            float4 a0 = *(float4*)&As[k][ty * 8];
            float4 a1 = *(float4*)&As[k][ty * 8 + 4];
            float4 b0 = *(float4*)&Bs[k][tx * 8];
            float4 b1 = *(float4*)&Bs[k][tx * 8 + 4];
            float ar[8] = {a0.x, a0.y, a0.z, a0.w, a1.x, a1.y, a1.z, a1.w};
            float br[8] = {b0.x, b0.y, b0.z, b0.w, b1.x, b1.y, b1.z, b1.w};
#pragma unroll
            for (int i = 0; i < 8; i++)
#pragma unroll
                for (int j = 0; j < 8; j++) acc[i][j] += ar[i] * br[j];
        }
        __syncthreads();
    }

#pragma unroll
    for (int i = 0; i < 8; i++) {
        const int row = bm + ty * 8 + i;
#pragma unroll
        for (int j = 0; j < 8; j += 4) {
            const int col = bn + tx * 8 + j;
            float4 v;
            v.x = acc[i][j + 0] + bias[col + 0];
            v.y = acc[i][j + 1] + bias[col + 1];
            v.z = acc[i][j + 2] + bias[col + 2];
            v.w = acc[i][j + 3] + bias[col + 3];
            *(float4*)(g_Xg + (size_t)row * N + col) = v;
        }
    }
}

// ---------------------------------------------------------------------------
// P2: g_Xr[row, j] = sum_k x[row, k] * Wrx[k, j]   (M=16384, N=100, K=512)
// Block handles 16 rows; x tile in shared; Wrx value reused across 16 rows.
// ---------------------------------------------------------------------------
__global__ __launch_bounds__(128) void p2_xwrx_kernel(
    const float* __restrict__ x, const float* __restrict__ Wrx)
{
    __shared__ float xs[16][cI];   // 32 KB
    const int row0 = blockIdx.x * 16;
    const int tid = threadIdx.x;

    for (int i = tid; i < 16 * cI / 4; i += 128) {
        const int r = i / (cI / 4);
        const int c = i % (cI / 4);
        ((float4*)xs[r])[c] = ((const float4*)(x + (size_t)(row0 + r) * cI))[c];
    }
    __syncthreads();

    if (tid < cD) {
        float acc[16];
#pragma unroll
        for (int r = 0; r < 16; r++) acc[r] = 0.0f;
        for (int k = 0; k < cI; k += 4) {
            float w0 = Wrx[(k + 0) * cD + tid];
            float w1 = Wrx[(k + 1) * cD + tid];
            float w2 = Wrx[(k + 2) * cD + tid];
            float w3 = Wrx[(k + 3) * cD + tid];
#pragma unroll
            for (int r = 0; r < 16; r++) {
                float4 xv = *(float4*)&xs[r][k];
                acc[r] += xv.x * w0 + xv.y * w1 + xv.z * w2 + xv.w * w3;
            }
        }
#pragma unroll
        for (int r = 0; r < 16; r++)
            g_Xr[(size_t)(row0 + r) * cD + tid] = acc[r];
    }
}

// ---------------------------------------------------------------------------
// init: h = h0, c = c0, d = d0
// ---------------------------------------------------------------------------
__global__ void init_kernel(const float* __restrict__ h0,
                            const float* __restrict__ c0,
                            const float* __restrict__ d0)
{
    const int idx = blockIdx.x * blockDim.x + threadIdx.x;
    if (idx < cB * cH) {
        g_h[idx] = h0[idx];
        g_c[idx] = c0[idx];
    }
    if (idx < cB * cD) g_d[idx] = d0[idx];
}

// ---------------------------------------------------------------------------
// S1a: g_G[b,n] = g_Xg[t,b,n] + sum_k g_h[b,k] * Wh[k,n]
// M=64 (all of B), N=4096, K=1024. BM=64, BN=32, BK=16, 256 threads, 4x2/thr.
// grid = 128 blocks.
// ---------------------------------------------------------------------------
__global__ __launch_bounds__(256) void s1a_gates_kernel(
    const float* __restrict__ Wh, int t)
{
    constexpr int N = 4 * cH;   // 4096
    constexpr int K = cH;       // 1024

    __shared__ float As[16][64];
    __shared__ float Bs[16][32];

    const int tid = threadIdx.x;
    const int bn = blockIdx.x * 32;
    const int tx = tid & 15;   // n-group: cols tx*2..+1
    const int ty = tid >> 4;   // m-group: rows ty*4..+3

    float acc[4][2];
#pragma unroll
    for (int i = 0; i < 4; i++) { acc[i][0] = 0.0f; acc[i][1] = 0.0f; }

    const int arow = tid >> 2;        // 0..63
    const int acol = (tid & 3) * 4;   // 0,4,8,12
    const int brow = tid >> 4;        // 0..15
    const int bcol = (tid & 15) * 2;  // 0..30

    for (int k0 = 0; k0 < K; k0 += 16) {
        float4 a = *(const float4*)(g_h + (size_t)arow * K + k0 + acol);
        As[acol + 0][arow] = a.x;
        As[acol + 1][arow] = a.y;
        As[acol + 2][arow] = a.z;
        As[acol + 3][arow] = a.w;
        *(float2*)&Bs[brow][bcol] =
            *(const float2*)(Wh + (size_t)(k0 + brow) * N + bn + bcol);
        __syncthreads();
#pragma unroll
        for (int k = 0; k < 16; k++) {
            float4 av = *(float4*)&As[k][ty * 4];
            float2 bv = *(float2*)&Bs[k][tx * 2];
            acc[0][0] += av.x * bv.x;  acc[0][1] += av.x * bv.y;
            acc[1][0] += av.y * bv.x;  acc[1][1] += av.y * bv.y;
            acc[2][0] += av.z * bv.x;  acc[2][1] += av.z * bv.y;
            acc[3][0] += av.w * bv.x;  acc[3][1] += av.w * bv.y;
        }
        __syncthreads();
    }

    const float* add = g_Xg + (size_t)t * cB * N;
#pragma unroll
    for (int i = 0; i < 4; i++) {
        const int row = ty * 4 + i;
        const int col = bn + tx * 2;
        float2 v;
        v.x = acc[i][0] + add[(size_t)row * N + col + 0];
        v.y = acc[i][1] + add[(size_t)row * N + col + 1];
        *(float2*)(g_G + (size_t)row * N + col) = v;
    }
}

// ---------------------------------------------------------------------------
// S1b: r = sigmoid(g_Xr[t,b,:] + 0.5 * h@Wrh);  d := r * d   (in place)
// 64 blocks (one per b), 128 threads (j = tid < 100).
// ---------------------------------------------------------------------------
__global__ __launch_bounds__(128) void s1b_rd_kernel(
    const float* __restrict__ Wrh, int t)
{
    __shared__ float hs[cH];
    const int b = blockIdx.x;
    const int tid = threadIdx.x;

    for (int i = tid; i < cH / 4; i += 128)
        ((float4*)hs)[i] = ((const float4*)(g_h + (size_t)b * cH))[i];
    __syncthreads();

    if (tid < cD) {
        float a0 = 0.f, a1 = 0.f, a2 = 0.f, a3 = 0.f;
        for (int k = 0; k < cH; k += 4) {
            a0 += hs[k + 0] * Wrh[(k + 0) * cD + tid];
            a1 += hs[k + 1] * Wrh[(k + 1) * cD + tid];
            a2 += hs[k + 2] * Wrh[(k + 2) * cD + tid];
            a3 += hs[k + 3] * Wrh[(k + 3) * cD + tid];
        }
        const float pre = g_Xr[(size_t)t * cB * cD + b * cD + tid]
                        + cALPHA * ((a0 + a1) + (a2 + a3));
        const float r = sigmoidf_(pre);
        g_d[b * cD + tid] = r * g_d[b * cD + tid];
    }
}

// ---------------------------------------------------------------------------
// S2: u = d_new @ Wd;  c := sig(f)*c + sig(i)*tanh(g) + tanh(u);
//     h := sig(o)*tanh(c);  out[t] = h
// 64 blocks (one per b), 256 threads, 4 hidden elems per thread.
// ---------------------------------------------------------------------------
__global__ __launch_bounds__(256) void s2_update_kernel(
    const float* __restrict__ Wd, float* __restrict__ out, int t)
{
    __shared__ float dn[cD];
    const int b = blockIdx.x;
    const int tid = threadIdx.x;

    if (tid < cD) dn[tid] = g_d[b * cD + tid];
    __syncthreads();

    float u[4] = {0.f, 0.f, 0.f, 0.f};
    for (int j = 0; j < cD; j++) {
        const float dv = dn[j];
        const float* wrow = Wd + (size_t)j * cH + tid;
        u[0] += dv * wrow[0];
        u[1] += dv * wrow[256];
        u[2] += dv * wrow[512];
        u[3] += dv * wrow[768];
    }

    const float* Gb = g_G + (size_t)b * 4 * cH;
#pragma unroll
    for (int rep = 0; rep < 4; rep++) {
        const int hx = tid + rep * 256;
        const float ig = sigmoidf_(Gb[hx]);
        const float fg = sigmoidf_(Gb[cH + hx]);
        const float gg = tanhf(Gb[2 * cH + hx]);
        const float og = sigmoidf_(Gb[3 * cH + hx]);
        float c = fg * g_c[(size_t)b * cH + hx] + ig * gg + tanhf(u[rep]);
        g_c[(size_t)b * cH + hx] = c;
        const float hn = og * tanhf(c);
        g_h[(size_t)b * cH + hx] = hn;
        out[(size_t)t * cB * cH + (size_t)b * cH + hx] = hn;
    }
}

// ---------------------------------------------------------------------------
// finalize: append final h, c, d after the T*B*H outputs
// ---------------------------------------------------------------------------
__global__ void finalize_kernel(float* __restrict__ out)
{
    const int idx = blockIdx.x * blockDim.x + threadIdx.x;
    const size_t base = (size_t)cT * cB * cH;
    if (idx < cB * cH) {
        out[base + idx] = g_h[idx];
        out[base + cB * cH + idx] = g_c[idx];
    }
    if (idx < cB * cD) out[base + 2 * (size_t)cB * cH + idx] = g_d[idx];
}

// ---------------------------------------------------------------------------
extern "C" void kernel_launch(void* const* d_in, const int* in_sizes, int n_in,
                              void* d_out, int out_size)
{
    const float* x   = (const float*)d_in[0];
    const float* h0  = (const float*)d_in[1];
    const float* c0  = (const float*)d_in[2];
    const float* d0  = (const float*)d_in[3];
    const float* Wx  = (const float*)d_in[4];
    const float* Wh  = (const float*)d_in[5];
    const float* bb  = (const float*)d_in[6];
    const float* Wrx = (const float*)d_in[7];
    const float* Wrh = (const float*)d_in[8];
    const float* Wd  = (const float*)d_in[9];
    float* out = (float*)d_out;

    // init state
    init_kernel<<<(cB * cH + 255) / 256, 256>>>(h0, c0, d0);

    // precompute input projections (parallel over all T)
    {
        dim3 grid(4 * cH / 128, cT * cB / 128);  // (32, 128)
        p1_xwx_kernel<<<grid, 256>>>(x, Wx, bb);
    }
    p2_xwrx_kernel<<<cT * cB / 16, 128>>>(x, Wrx);

    // sequential scan
    for (int t = 0; t < cT; t++) {
        s1a_gates_kernel<<<128, 256>>>(Wh, t);
        s1b_rd_kernel<<<cB, 128>>>(Wrh, t);
        s2_update_kernel<<<cB, 256>>>(Wd, out, t);
    }

    // tail: final h, c, d (only if the harness expects them)
    const long long full = (long long)cT * cB * cH + 2LL * cB * cH + (long long)cB * cD;
    if ((long long)out_size >= full)
        finalize_kernel<<<(cB * cH + 255) / 256, 256>>>(out);
}

// round 9
// speedup vs baseline: 1.1413x; 1.1392x over previous
#include <cuda_runtime.h>
#include <cuda_bf16.h>
#include <math.h>
#include <stdint.h>

// Problem constants
constexpr int cT = 256;
constexpr int cB = 64;
constexpr int cI = 512;
constexpr int cH = 1024;
constexpr int cD = 100;
constexpr int N4H = 4 * cH;  // 4096

constexpr int NBLK = 144;        // persistent blocks (<=148 SMs, 1/SM via smem)
constexpr int GEMM_BLKS = 128;   // N4H / 32
constexpr int NTHR = 256;

// dynamic smem layout (floats):
//   ws      [0, 32768)        Wh tile 1024x32 (gemm blocks only; persists)
//   scratch [32768, 40032)    phase-dependent
constexpr int SCR_OFF = 32768;
constexpr int SMEM_BYTES = (32768 + 7296) * 4;   // 160,256 B

using u64 = unsigned long long;

// ---------------- scratch (device globals; no allocation allowed) ----------
__device__ float g_Xg[(size_t)cT * cB * N4H];   // x@Wx + b [T,B,4H]
__device__ float g_Xr[(size_t)cT * cB * cD];    // x@Wrx    [T,B,D]
__device__ float g_G [(size_t)cB * N4H];        // gate preacts [B,4H]
__device__ float g_h [cB * cH];                 // h, b-major
__device__ float g_hT[cH * cB];                 // h, k-major (for GEMM A staging)
__device__ float g_c [cB * cH];
__device__ float g_d [cB * cD];
__device__ unsigned g_gen;
__device__ unsigned g_cnt;

__device__ __forceinline__ float sigmoidf_(float x) {
    return 1.0f / (1.0f + expf(-x));
}

// packed fp32x2 helpers (sm_100+: fma.rn.f32x2, PTX-only)
__device__ __forceinline__ u64 dup_f32(float x) {
    u64 r; unsigned u = __float_as_uint(x);
    asm("mov.b64 %0, {%1, %1};" : "=l"(r) : "r"(u));
    return r;
}
__device__ __forceinline__ void ffma2(u64& a, u64 x, u64 y) {
    asm("fma.rn.f32x2 %0, %1, %2, %0;" : "+l"(a) : "l"(x), "l"(y));
}
__device__ __forceinline__ float2 unpk(u64 v) {
    unsigned lo, hi;
    asm("mov.b64 {%0, %1}, %2;" : "=r"(lo), "=r"(hi) : "l"(v));
    return make_float2(__uint_as_float(lo), __uint_as_float(hi));
}

// grid barrier: all NBLK blocks resident (1 block/SM enforced by smem)
__device__ __forceinline__ void gridbar() {
    __syncthreads();
    if (threadIdx.x == 0) {
        __threadfence();
        volatile unsigned* genp = &g_gen;
        unsigned gen = *genp;
        if (atomicAdd(&g_cnt, 1u) == NBLK - 1) {
            g_cnt = 0;
            __threadfence();
            *genp = gen + 1;
        } else {
            while (*genp == gen) { }
            __threadfence();
        }
    }
    __syncthreads();
}

// ---------------------------------------------------------------------------
// P1: g_Xg = x @ Wx + b   (M=16384, N=4096, K=512) — 128x128x8 fp32 tiles
// ---------------------------------------------------------------------------
__global__ __launch_bounds__(256) void p1_xwx_kernel(
    const float* __restrict__ A, const float* __restrict__ Bm,
    const float* __restrict__ bias)
{
    constexpr int N = N4H;
    constexpr int K = cI;

    __shared__ float As[8][128];
    __shared__ float Bs[8][128];

    const int tid = threadIdx.x;
    const int bm = blockIdx.y * 128;
    const int bn = blockIdx.x * 128;
    const int tx = tid & 15;
    const int ty = tid >> 4;

    float acc[8][8];
#pragma unroll
    for (int i = 0; i < 8; i++)
#pragma unroll
        for (int j = 0; j < 8; j++) acc[i][j] = 0.0f;

    const int arow = tid >> 1;
    const int acol = (tid & 1) * 4;
    const int brow = tid >> 5;
    const int bcol = (tid & 31) * 4;

    for (int k0 = 0; k0 < K; k0 += 8) {
        float4 a = *(const float4*)(A + (size_t)(bm + arow) * K + k0 + acol);
        As[acol + 0][arow] = a.x;
        As[acol + 1][arow] = a.y;
        As[acol + 2][arow] = a.z;
        As[acol + 3][arow] = a.w;
        *(float4*)(&Bs[brow][bcol]) =
            *(const float4*)(Bm + (size_t)(k0 + brow) * N + bn + bcol);
        __syncthreads();
#pragma unroll
        for (int k = 0; k < 8; k++) {
            float4 a0 = *(float4*)&As[k][ty * 8];
            float4 a1 = *(float4*)&As[k][ty * 8 + 4];
            float4 b0 = *(float4*)&Bs[k][tx * 8];
            float4 b1 = *(float4*)&Bs[k][tx * 8 + 4];
            float ar[8] = {a0.x, a0.y, a0.z, a0.w, a1.x, a1.y, a1.z, a1.w};
            float br[8] = {b0.x, b0.y, b0.z, b0.w, b1.x, b1.y, b1.z, b1.w};
#pragma unroll
            for (int i = 0; i < 8; i++)
#pragma unroll
                for (int j = 0; j < 8; j++) acc[i][j] += ar[i] * br[j];
        }
        __syncthreads();
    }

#pragma unroll
    for (int i = 0; i < 8; i++) {
        const int row = bm + ty * 8 + i;
#pragma unroll
        for (int j = 0; j < 8; j += 4) {
            const int col = bn + tx * 8 + j;
            float4 v;
            v.x = acc[i][j + 0] + bias[col + 0];
            v.y = acc[i][j + 1] + bias[col + 1];
            v.z = acc[i][j + 2] + bias[col + 2];
            v.w = acc[i][j + 3] + bias[col + 3];
            *(float4*)(g_Xg + (size_t)row * N + col) = v;
        }
    }
}

// ---------------------------------------------------------------------------
// P2: g_Xr = x @ Wrx   (M=16384, N=100, K=512)
// ---------------------------------------------------------------------------
__global__ __launch_bounds__(128) void p2_xwrx_kernel(
    const float* __restrict__ x, const float* __restrict__ Wrx)
{
    __shared__ float xs[16][cI];
    const int row0 = blockIdx.x * 16;
    const int tid = threadIdx.x;

    for (int i = tid; i < 16 * cI / 4; i += 128) {
        const int r = i / (cI / 4);
        const int c = i % (cI / 4);
        ((float4*)xs[r])[c] = ((const float4*)(x + (size_t)(row0 + r) * cI))[c];
    }
    __syncthreads();

    if (tid < cD) {
        float acc[16];
#pragma unroll
        for (int r = 0; r < 16; r++) acc[r] = 0.0f;
        for (int k = 0; k < cI; k += 4) {
            float w0 = Wrx[(k + 0) * cD + tid];
            float w1 = Wrx[(k + 1) * cD + tid];
            float w2 = Wrx[(k + 2) * cD + tid];
            float w3 = Wrx[(k + 3) * cD + tid];
#pragma unroll
            for (int r = 0; r < 16; r++) {
                float4 xv = *(float4*)&xs[r][k];
                acc[r] += xv.x * w0 + xv.y * w1 + xv.z * w2 + xv.w * w3;
            }
        }
#pragma unroll
        for (int r = 0; r < 16; r++)
            g_Xr[(size_t)(row0 + r) * cD + tid] = acc[r];
    }
}

// ---------------------------------------------------------------------------
// Persistent fused scan kernel
// blocks 0..127 : gates GEMM (Wh tile resident in SMEM) then c/h update
// blocks 128..143: r/d path (h@Wrh)
// ---------------------------------------------------------------------------
__global__ __launch_bounds__(NTHR, 1) void scan_kernel(
    const float* __restrict__ Wh,  const float* __restrict__ Wrh,
    const float* __restrict__ Wd,  const float* __restrict__ h0,
    const float* __restrict__ c0,  const float* __restrict__ d0,
    float* __restrict__ out, int has_tail)
{
    extern __shared__ float smem[];
    float* ws  = smem;            // 1024x32 Wh tile (gemm blocks)
    float* scr = smem + SCR_OFF;  // phase scratch

    const int blk = blockIdx.x;
    const int tid = threadIdx.x;

    // ---- one-time: state init (all blocks, grid-stride) ----
    for (int i = blk * NTHR + tid; i < cB * cH; i += NBLK * NTHR) {
        float hv = h0[i];
        g_h[i] = hv;
        g_c[i] = c0[i];
        g_hT[(i & (cH - 1)) * cB + (i >> 10)] = hv;
    }
    for (int i = blk * NTHR + tid; i < cB * cD; i += NBLK * NTHR)
        g_d[i] = d0[i];

    // ---- one-time: stage Wh tile ----
    if (blk < GEMM_BLKS) {
        const int bn = blk * 32;
        for (int i = tid; i < cH * 32; i += NTHR) {
            const int k = i >> 5, c = i & 31;
            ws[i] = Wh[(size_t)k * N4H + bn + c];
        }
    }
    gridbar();

    // gemm thread mapping
    const int cg = tid & 15;   // col pair: c0 = cg*2
    const int rg = tid >> 4;   // row quad: r0 = rg*4

    for (int t = 0; t < cT; t++) {
        // ================= PHASE 1 =================
        if (blk < GEMM_BLKS) {
            // G[b][bn+c] = Xg[t][b][bn+c] + sum_k h[b][k]*Wh[k][bn+c]
            u64 acc00 = 0, acc01 = 0, acc10 = 0, acc11 = 0;

            // prologue: stage chunk 0 of h^T (32 k x 64 b)
            {
                const float4* src = (const float4*)g_hT;
                float4* dst = (float4*)scr;
                dst[tid] = src[tid];
                dst[tid + 256] = src[tid + 256];
            }
            __syncthreads();

            int buf = 0;
            for (int c = 0; c < 32; c++) {
                const float* hsc = scr + buf * 2048;
                if (c < 31) {  // prefetch next chunk into other buffer
                    const float4* src = (const float4*)(g_hT + (c + 1) * 2048);
                    float4* dst = (float4*)(scr + (buf ^ 1) * 2048);
                    dst[tid] = src[tid];
                    dst[tid + 256] = src[tid + 256];
                }
                const int k0 = c * 32;
#pragma unroll
                for (int kk = 0; kk < 32; kk++) {
                    ulonglong2 av = *(const ulonglong2*)&hsc[kk * 64 + rg * 4];
                    float2 bv = *(const float2*)&ws[(k0 + kk) * 32 + cg * 2];
                    u64 b0d = dup_f32(bv.x);
                    u64 b1d = dup_f32(bv.y);
                    ffma2(acc00, av.x, b0d);
                    ffma2(acc01, av.x, b1d);
                    ffma2(acc10, av.y, b0d);
                    ffma2(acc11, av.y, b1d);
                }
                __syncthreads();
                buf ^= 1;
            }

            // epilogue: add Xg, store G
            const float2 p00 = unpk(acc00), p01 = unpk(acc01);
            const float2 p10 = unpk(acc10), p11 = unpk(acc11);
            const int col = blk * 32 + cg * 2;
            const int r0 = rg * 4;
            const float* xg = g_Xg + ((size_t)t * cB) * N4H;
            float2 res, xv;
            xv = *(const float2*)&xg[(size_t)(r0 + 0) * N4H + col];
            res = make_float2(p00.x + xv.x, p01.x + xv.y);
            *(float2*)&g_G[(size_t)(r0 + 0) * N4H + col] = res;
            xv = *(const float2*)&xg[(size_t)(r0 + 1) * N4H + col];
            res = make_float2(p00.y + xv.x, p01.y + xv.y);
            *(float2*)&g_G[(size_t)(r0 + 1) * N4H + col] = res;
            xv = *(const float2*)&xg[(size_t)(r0 + 2) * N4H + col];
            res = make_float2(p10.x + xv.x, p11.x + xv.y);
            *(float2*)&g_G[(size_t)(r0 + 2) * N4H + col] = res;
            xv = *(const float2*)&xg[(size_t)(r0 + 3) * N4H + col];
            res = make_float2(p10.y + xv.x, p11.y + xv.y);
            *(float2*)&g_G[(size_t)(r0 + 3) * N4H + col] = res;
        } else {
            // r/d path: 16 blocks x 4 b each; 2 warps per b
            const int bb0 = (blk - GEMM_BLKS) * 4;
            float* hs4 = scr;  // 4 x 1024
            for (int i = tid; i < 4 * cH; i += NTHR)
                hs4[i] = g_h[(size_t)bb0 * cH + i];
            __syncthreads();

            const int w = tid >> 5, lane = tid & 31;
            const int bl = w >> 1, half = w & 1;
            const int b = bb0 + bl;
            const float* hb = hs4 + bl * cH;
            const int j1 = half * 32 + lane;        // 0..63
            const int j2 = 64 + half * 32 + lane;   // 64..127 (mask >=100)
            const int j2c = (j2 < cD) ? j2 : (cD - 1);

            float a1 = 0.f, a2 = 0.f;
#pragma unroll 4
            for (int k = 0; k < cH; k++) {
                const float hv = hb[k];
                const float* wr = Wrh + (size_t)k * cD;
                a1 += hv * wr[j1];
                a2 += hv * wr[j2c];
            }
            {
                const float x1 = g_Xr[(size_t)t * cB * cD + b * cD + j1];
                const float r1 = sigmoidf_(x1 + 0.5f * a1);
                g_d[b * cD + j1] = r1 * g_d[b * cD + j1];
            }
            if (j2 < cD) {
                const float x2 = g_Xr[(size_t)t * cB * cD + b * cD + j2];
                const float r2 = sigmoidf_(x2 + 0.5f * a2);
                g_d[b * cD + j2] = r2 * g_d[b * cD + j2];
            }
        }
        gridbar();

        // ================= PHASE 2 =================
        if (blk < GEMM_BLKS) {
            // block handles hx range [blk*8, blk*8+8) for all 64 b
            const int hx0 = blk * 8;
            float* ds = scr;              // 64 x 101 (padded)
            float* wt = scr + 64 * 101;   // 100 x 8

            for (int i = tid; i < cB * cD; i += NTHR)
                ds[(i / cD) * 101 + (i % cD)] = g_d[i];
            for (int i = tid; i < cD * 8; i += NTHR) {
                const int j = i >> 3, c = i & 7;
                wt[i] = Wd[(size_t)j * cH + hx0 + c];
            }
            __syncthreads();

            const int b = tid >> 2;        // 0..63
            const int hq = tid & 3;        // 0..3
            const int hx = hx0 + hq * 2;

            float u0 = 0.f, u1 = 0.f;
            const float* dsb = ds + b * 101;
#pragma unroll 4
            for (int j = 0; j < cD; j++) {
                const float dv = dsb[j];
                const float2 w2 = *(const float2*)&wt[j * 8 + hq * 2];
                u0 += dv * w2.x;
                u1 += dv * w2.y;
            }

            const float* Gb = g_G + (size_t)b * N4H;
            const float2 gi = *(const float2*)&Gb[hx];
            const float2 gf = *(const float2*)&Gb[cH + hx];
            const float2 gg = *(const float2*)&Gb[2 * cH + hx];
            const float2 go = *(const float2*)&Gb[3 * cH + hx];
            const float2 cold = *(const float2*)&g_c[b * cH + hx];

            const float cn0 = sigmoidf_(gf.x) * cold.x
                            + sigmoidf_(gi.x) * tanhf(gg.x) + tanhf(u0);
            const float cn1 = sigmoidf_(gf.y) * cold.y
                            + sigmoidf_(gi.y) * tanhf(gg.y) + tanhf(u1);
            const float hn0 = sigmoidf_(go.x) * tanhf(cn0);
            const float hn1 = sigmoidf_(go.y) * tanhf(cn1);

            *(float2*)&g_c[b * cH + hx] = make_float2(cn0, cn1);
            *(float2*)&g_h[b * cH + hx] = make_float2(hn0, hn1);
            g_hT[(size_t)(hx + 0) * cB + b] = hn0;
            g_hT[(size_t)(hx + 1) * cB + b] = hn1;
            *(float2*)&out[((size_t)t * cB + b) * cH + hx] = make_float2(hn0, hn1);
        }
        gridbar();
    }

    // ---- tail: final h, c, d ----
    if (has_tail) {
        const size_t base = (size_t)cT * cB * cH;
        for (int i = blk * NTHR + tid; i < cB * cH; i += NBLK * NTHR) {
            out[base + i] = g_h[i];
            out[base + cB * cH + i] = g_c[i];
        }
        for (int i = blk * NTHR + tid; i < cB * cD; i += NBLK * NTHR)
            out[base + 2 * (size_t)cB * cH + i] = g_d[i];
    }
}

// ---------------------------------------------------------------------------
extern "C" void kernel_launch(void* const* d_in, const int* in_sizes, int n_in,
                              void* d_out, int out_size)
{
    const float* x   = (const float*)d_in[0];
    const float* h0  = (const float*)d_in[1];
    const float* c0  = (const float*)d_in[2];
    const float* d0  = (const float*)d_in[3];
    const float* Wx  = (const float*)d_in[4];
    const float* Wh  = (const float*)d_in[5];
    const float* bb  = (const float*)d_in[6];
    const float* Wrx = (const float*)d_in[7];
    const float* Wrh = (const float*)d_in[8];
    const float* Wd  = (const float*)d_in[9];
    float* out = (float*)d_out;

    static bool attr_set = false;
    if (!attr_set) {
        cudaFuncSetAttribute(scan_kernel,
                             cudaFuncAttributeMaxDynamicSharedMemorySize,
                             SMEM_BYTES);
        attr_set = true;
    }

    // precompute input projections (fully parallel over T)
    {
        dim3 grid(N4H / 128, cT * cB / 128);
        p1_xwx_kernel<<<grid, 256>>>(x, Wx, bb);
    }
    p2_xwrx_kernel<<<cT * cB / 16, 128>>>(x, Wrx);

    // fused persistent scan
    const long long full = (long long)cT * cB * cH + 2LL * cB * cH
                         + (long long)cB * cD;
    const int has_tail = ((long long)out_size >= full) ? 1 : 0;
    scan_kernel<<<NBLK, NTHR, SMEM_BYTES>>>(Wh, Wrh, Wd, h0, c0, d0,
                                            out, has_tail);
}